// round 13
// baseline (speedup 1.0000x reference)
#include <cuda_runtime.h>

// Problem constants
#define NN   50000
#define EE   800000
#define INCH 256
#define EDIM 32
#define HH   4
#define CC   32
#define HC   128

typedef unsigned long long u64;

// ---------------- scratch (device globals: no allocation allowed) ----------
__device__ __align__(16) float g_xf[(size_t)NN * 256]; // [node][0:128=x_src | 128:256=x_dst]
__device__ __align__(16) float g_m[NN * HH];           // segment max (bit-init 0xFF = "-inf" trick)
__device__ __align__(16) float g_s[NN * HH];           // segment sum
__device__ __align__(16) int   g_ei[2 * EE];           // normalized int32 edge_index
__device__ int g_idx64;                                 // 1 if input edge_index is int64
// fallback homes for alpha outputs if d_out is too small to hold them
__device__ __align__(16) float g_an[(size_t)EE * HH];
__device__ __align__(16) float g_ar[(size_t)EE * HH];

// ---------------- packed fp32x2 helpers (Blackwell FFMA2) ------------------
__device__ __forceinline__ u64 pk2(float lo, float hi) {
    u64 r;
    asm("mov.b64 %0, {%1, %2};" : "=l"(r) : "r"(__float_as_uint(lo)), "r"(__float_as_uint(hi)));
    return r;
}
__device__ __forceinline__ float2 upk2(u64 v) {
    unsigned int a, b;
    asm("mov.b64 {%0, %1}, %2;" : "=r"(a), "=r"(b) : "l"(v));
    return make_float2(__uint_as_float(a), __uint_as_float(b));
}
__device__ __forceinline__ u64 ffma2(u64 a, u64 b, u64 c) {
    u64 d;
    asm("fma.rn.f32x2 %0, %1, %2, %3;" : "=l"(d) : "l"(a), "l"(b), "l"(c));
    return d;
}

__device__ __forceinline__ float tanh_f(float x) {
    // exact at extremes, ~1e-6 abs error mid-range; independent of fast-math flags
    float e = __expf(2.0f * x);
    return 1.0f - 2.0f / (e + 1.0f);
}

// Branch-free float atomic max via int/uint monotone mapping.
// Requires init bit pattern 0xFFFFFFFF (acts below every float in both orders).
__device__ __forceinline__ void atomicMaxF(float* addr, float v) {
    if (v >= 0.0f) atomicMax((int*)addr, __float_as_int(v));
    else           atomicMin((unsigned int*)addr, __float_as_uint(v));
}

// ======================================================================
// Kernel 0a: detect edge_index dtype.
// Node ids < 50000 < 2^16, so for int64 every odd 32-bit word is 0.
// ======================================================================
__global__ void detect_idx(const int* __restrict__ ei32) {
    int t = threadIdx.x;                 // 256 threads
    int v = ei32[2 * t + 1];
    int any = __syncthreads_or(v != 0);
    if (t == 0) g_idx64 = (any == 0) ? 1 : 0;
}

// ======================================================================
// Kernel 0b: normalize edge_index -> int32 g_ei[2*EE]
// ======================================================================
__global__ __launch_bounds__(256) void convert_idx(const void* __restrict__ ei) {
    int i = blockIdx.x * 256 + threadIdx.x;
    if (i >= 2 * EE) return;
    if (g_idx64) g_ei[i] = (int)((const long long*)ei)[i];
    else         g_ei[i] = ((const int*)ei)[i];
}

// ======================================================================
// Kernel 1: node GEMM  g_xf = x @ [W_src | W_dst]   (50000x256 @ 256x256)
// 128x128 tile, BK=8, 256 threads, 8x8 micro-tile via FFMA2 (4 col-pairs)
// ======================================================================
__global__ __launch_bounds__(256) void gemm_node(const float* __restrict__ x,
                                                 const float* __restrict__ Wsrc,
                                                 const float* __restrict__ Wdst) {
    __shared__ __align__(16) u64   As2[8 * 128]; // [k][m], float duplicated in both halves
    __shared__ __align__(16) float Bs[8 * 128];  // [k][n]

    const int cb = blockIdx.y;                  // 0 -> W_src cols, 1 -> W_dst cols
    const float* __restrict__ W = cb ? Wdst : Wsrc;
    const int m0 = blockIdx.x * 128;
    const int t  = threadIdx.x;
    const int tx = t & 15;        // n-group (8 cols = 4 pairs)
    const int ty = t >> 4;        // m-group (8 rows)

    u64 acc[8][4];
#pragma unroll
    for (int i = 0; i < 8; i++)
#pragma unroll
        for (int j = 0; j < 4; j++) acc[i][j] = 0ULL;

    const int ar = t >> 1;            // A tile row 0..127
    const int ak = (t & 1) * 4;       // A tile k offset
    const int bk = t >> 5;            // B tile k row 0..7
    const int bc = (t & 31) * 4;      // B tile col

    const int arow = m0 + ar;
    const bool a_ok = (arow < NN);

    for (int k0 = 0; k0 < 256; k0 += 8) {
        float4 av = make_float4(0.f, 0.f, 0.f, 0.f);
        if (a_ok) av = *(const float4*)&x[(size_t)arow * 256 + k0 + ak];
        float4 bv = *(const float4*)&W[(size_t)(k0 + bk) * 128 + bc];

        __syncthreads();
        As2[(ak + 0) * 128 + ar] = pk2(av.x, av.x);
        As2[(ak + 1) * 128 + ar] = pk2(av.y, av.y);
        As2[(ak + 2) * 128 + ar] = pk2(av.z, av.z);
        As2[(ak + 3) * 128 + ar] = pk2(av.w, av.w);
        *(float4*)&Bs[bk * 128 + bc] = bv;
        __syncthreads();

#pragma unroll
        for (int k = 0; k < 8; k++) {
            u64 a2[8];
#pragma unroll
            for (int i = 0; i < 8; i++) a2[i] = As2[k * 128 + ty * 8 + i];
            const u64* bp = (const u64*)&Bs[k * 128 + tx * 8];
            u64 b2[4];
#pragma unroll
            for (int j = 0; j < 4; j++) b2[j] = bp[j];
#pragma unroll
            for (int i = 0; i < 8; i++)
#pragma unroll
                for (int j = 0; j < 4; j++) acc[i][j] = ffma2(a2[i], b2[j], acc[i][j]);
        }
    }

#pragma unroll
    for (int i = 0; i < 8; i++) {
        int row = m0 + ty * 8 + i;
        if (row < NN) {
            u64* op = (u64*)&g_xf[(size_t)row * 256 + cb * 128 + tx * 8];
#pragma unroll
            for (int j = 0; j < 4; j++) op[j] = acc[i][j];
        }
    }
}

// ======================================================================
// Kernel 2 (fused): e_feat GEMM + attention logits + decay + segment max
//   block = 256 threads = 8 warps; each warp owns 8 edges (64 per block).
//   Lane l owns channels [4l, 4l+4)  (head = l>>3).
//   edge_attr rows staged in smem; operands broadcast via LDS.128 (no SHFL).
// ======================================================================
__global__ __launch_bounds__(256) void edge_attn(const float* __restrict__ eattr,
                                                 const float* __restrict__ dw,
                                                 const float* __restrict__ Wedge,
                                                 const float* __restrict__ att,
                                                 const float* __restrict__ sscale,
                                                 float* __restrict__ araw,
                                                 float* __restrict__ adec) {
    __shared__ __align__(16) float4 Es[64 * 8]; // 64 edges x 32 floats = 8KB

    const int t = threadIdx.x;
    // stage this block's 64 edge_attr rows (coalesced, identity layout)
    const float4* ea4 = (const float4*)(eattr + (size_t)blockIdx.x * 64 * 32);
    Es[t]       = ea4[t];
    Es[t + 256] = ea4[t + 256];
    __syncthreads();

    const int w = t >> 5, l = t & 31;
    const int e0 = blockIdx.x * 64 + w * 8;

    const float4 att4 = *(const float4*)&att[4 * l];
    const float  sc   = sscale[l >> 3];

    // -------- phase A: e_feat for 8 edges x 4 channels, FFMA2 ----------
    u64 acc[8][2];
#pragma unroll
    for (int j = 0; j < 8; j++) { acc[j][0] = 0ULL; acc[j][1] = 0ULL; }

#pragma unroll
    for (int k0 = 0; k0 < 8; k0++) {
        // this lane's 4 W_edge columns for k = 4k0..4k0+3 (L1-resident)
        u64 wr[4][2];
#pragma unroll
        for (int kk = 0; kk < 4; kk++) {
            float4 w4 = *(const float4*)&Wedge[(size_t)(4 * k0 + kk) * 128 + 4 * l];
            wr[kk][0] = pk2(w4.x, w4.y);
            wr[kk][1] = pk2(w4.z, w4.w);
        }
#pragma unroll
        for (int j = 0; j < 8; j++) {
            float4 a4 = Es[(w * 8 + j) * 8 + k0];   // smem broadcast
            u64 a0 = pk2(a4.x, a4.x), a1 = pk2(a4.y, a4.y);
            u64 a2 = pk2(a4.z, a4.z), a3 = pk2(a4.w, a4.w);
            acc[j][0] = ffma2(a0, wr[0][0], acc[j][0]);
            acc[j][1] = ffma2(a0, wr[0][1], acc[j][1]);
            acc[j][0] = ffma2(a1, wr[1][0], acc[j][0]);
            acc[j][1] = ffma2(a1, wr[1][1], acc[j][1]);
            acc[j][0] = ffma2(a2, wr[2][0], acc[j][0]);
            acc[j][1] = ffma2(a2, wr[2][1], acc[j][1]);
            acc[j][0] = ffma2(a3, wr[3][0], acc[j][0]);
            acc[j][1] = ffma2(a3, wr[3][1], acc[j][1]);
        }
    }

    // -------- phase B: tanh + att-dot + per-head reduce + decay --------
#pragma unroll
    for (int j = 0; j < 8; j++) {
        const int ge  = e0 + j;
        const int src = g_ei[ge];
        const int dst = g_ei[EE + ge];

        float4 xs = *(const float4*)&g_xf[(size_t)src * 256 + 4 * l];
        float4 xd = *(const float4*)&g_xf[(size_t)dst * 256 + 128 + 4 * l];
        float2 e01 = upk2(acc[j][0]);
        float2 e23 = upk2(acc[j][1]);

        float p = tanh_f(xs.x + xd.x + e01.x) * att4.x
                + tanh_f(xs.y + xd.y + e01.y) * att4.y
                + tanh_f(xs.z + xd.z + e23.x) * att4.z
                + tanh_f(xs.w + xd.w + e23.y) * att4.w;

        // reduce over the 8 lanes of this head -> every lane has its head's sum
        p += __shfl_xor_sync(0xffffffffu, p, 1);
        p += __shfl_xor_sync(0xffffffffu, p, 2);
        p += __shfl_xor_sync(0xffffffffu, p, 4);

        // spatial decay (per lane's head)
        float dwj = dw[ge];
        float dec = __expf(sc * __logf(dwj));
        float ad  = p * dec;

        // head leaders (lanes 0,8,16,24) store scalars directly: 4 scalar
        // stores to consecutive addresses coalesce into one 16B transaction
        if ((l & 7) == 0) {
            const int h = l >> 3;
            araw[(size_t)ge * 4 + h] = p;
            adec[(size_t)ge * 4 + h] = ad;
            atomicMaxF(&g_m[dst * 4 + h], ad);
        }
    }
}

// ======================================================================
// Kernel 3: ea = exp(alpha - m[dst]); s[dst] += ea.  One thread per edge,
//           float4 across the 4 heads + one red.v4 per edge.
// ======================================================================
__global__ __launch_bounds__(256) void pass_exp(float* __restrict__ buf) {
    int e = blockIdx.x * 256 + threadIdx.x;
    if (e >= EE) return;
    int dst = g_ei[EE + e];
    float4 a = *(const float4*)&buf[(size_t)e * 4];
    float4 m = *(const float4*)&g_m[dst * 4];
    float4 ea;
    ea.x = __expf(a.x - m.x);
    ea.y = __expf(a.y - m.y);
    ea.z = __expf(a.z - m.z);
    ea.w = __expf(a.w - m.w);
    *(float4*)&buf[(size_t)e * 4] = ea;
    float* sp = &g_s[dst * 4];
    asm volatile("red.global.add.v4.f32 [%0], {%1, %2, %3, %4};"
                 :: "l"(sp), "f"(ea.x), "f"(ea.y), "f"(ea.z), "f"(ea.w)
                 : "memory");
}

// ======================================================================
// Kernel 4: normalize + aggregate.  One warp per edge.
//   alpha_norm = ea/(s[dst]+1e-8) (written back to buf)
//   out[dst, ch] += x_src[src, ch] * alpha_norm[head(ch)]   via red.v4.f32
// ======================================================================
__global__ __launch_bounds__(256) void pass_agg(float* __restrict__ buf,
                                                float* __restrict__ outf) {
    int gw = (blockIdx.x * 256 + threadIdx.x) >> 5;
    if (gw >= EE) return;
    int l  = threadIdx.x & 31;
    int ge = gw;
    int src = g_ei[ge];
    int dst = g_ei[EE + ge];

    float4 ea4 = *(const float4*)&buf[(size_t)ge * 4];
    float4 s4  = *(const float4*)&g_s[dst * 4];
    float4 an;
    an.x = ea4.x / (s4.x + 1e-8f);
    an.y = ea4.y / (s4.y + 1e-8f);
    an.z = ea4.z / (s4.z + 1e-8f);
    an.w = ea4.w / (s4.w + 1e-8f);
    if (l == 0) *(float4*)&buf[(size_t)ge * 4] = an;

    float anh = (l < 8) ? an.x : (l < 16) ? an.y : (l < 24) ? an.z : an.w;
    float4 xs = *(const float4*)&g_xf[(size_t)src * 256 + 4 * l];

    float* dp = &outf[(size_t)dst * 128 + 4 * l];
    asm volatile("red.global.add.v4.f32 [%0], {%1, %2, %3, %4};"
                 :: "l"(dp), "f"(xs.x * anh), "f"(xs.y * anh), "f"(xs.z * anh), "f"(xs.w * anh)
                 : "memory");
}

// ======================================================================
// Launch
// Inputs (metadata order):
//  0 x[N,256] f32 | 1 edge_index[2,E] int32 OR int64 (auto-detected)
//  2 edge_attr[E,32] f32 | 3 dist_weight[E] f32 | 4 W_src[256,128]
//  5 W_dst[256,128] | 6 W_edge[32,128] | 7 att[1,4,32] | 8 spatial_scale[4]
// Output: out[N*128] (+ alpha_norm[E*4] + alpha_raw[E*4] if out_size allows)
// ======================================================================
extern "C" void kernel_launch(void* const* d_in, const int* in_sizes, int n_in,
                              void* d_out, int out_size) {
    const float* x      = (const float*)d_in[0];
    const void*  ei     = d_in[1];
    const float* eattr  = (const float*)d_in[2];
    const float* dwv    = (const float*)d_in[3];
    const float* Wsrc   = (const float*)d_in[4];
    const float* Wdst   = (const float*)d_in[5];
    const float* Wedge  = (const float*)d_in[6];
    const float* att    = (const float*)d_in[7];
    const float* sscale = (const float*)d_in[8];

    float* outf = (float*)d_out; // [N,128] always first

    // alpha buffers: inside d_out if it can hold all three outputs, else scratch
    const long long full = (long long)NN * HC + 2LL * EE * HH; // 12,800,000
    float *anorm, *araw;
    if ((long long)out_size >= full) {
        anorm = outf + (size_t)NN * HC;
        araw  = anorm + (size_t)EE * HH;
    } else {
        void *pa = 0, *pr = 0;
        cudaGetSymbolAddress(&pa, g_an);
        cudaGetSymbolAddress(&pr, g_ar);
        anorm = (float*)pa;
        araw  = (float*)pr;
    }

    // init: out=0, m="-inf" bit pattern (0xFF), s=0
    cudaMemsetAsync(outf, 0, (size_t)NN * HC * sizeof(float), 0);
    void *pm = 0, *ps = 0;
    cudaGetSymbolAddress(&pm, g_m);
    cudaGetSymbolAddress(&ps, g_s);
    cudaMemsetAsync(pm, 0xFF, (size_t)NN * HH * sizeof(float), 0);
    cudaMemsetAsync(ps, 0x00, (size_t)NN * HH * sizeof(float), 0);

    detect_idx<<<1, 256>>>((const int*)ei);
    convert_idx<<<(2 * EE + 255) / 256, 256>>>(ei);
    gemm_node<<<dim3((NN + 127) / 128, 2), 256>>>(x, Wsrc, Wdst);
    edge_attn<<<EE / 64, 256>>>(eattr, dwv, Wedge, att, sscale, araw, anorm);
    pass_exp<<<(EE + 255) / 256, 256>>>(anorm);
    pass_agg<<<(EE * 32) / 256, 256>>>(anorm, outf);
}

// round 15
// speedup vs baseline: 1.1832x; 1.1832x over previous
#include <cuda_runtime.h>

// Problem constants
#define NN   50000
#define EE   800000
#define INCH 256
#define EDIM 32
#define HH   4
#define CC   32
#define HC   128

typedef unsigned long long u64;

// ---------------- scratch (device globals: no allocation allowed) ----------
__device__ __align__(16) float g_xf[(size_t)NN * 256]; // [node][0:128=x_src | 128:256=x_dst]
__device__ __align__(16) float g_m[NN * HH];           // segment max (bit-init 0xFF = "-inf" trick)
__device__ __align__(16) float g_s[NN * HH];           // segment sum
__device__ __align__(16) int   g_ei[2 * EE];           // normalized int32 edge_index
__device__ int g_idx64;                                 // 1 if input edge_index is int64
// fallback homes for alpha outputs if d_out is too small to hold them
__device__ __align__(16) float g_an[(size_t)EE * HH];
__device__ __align__(16) float g_ar[(size_t)EE * HH];

// ---------------- packed fp32x2 helpers (Blackwell FFMA2) ------------------
__device__ __forceinline__ u64 pk2(float lo, float hi) {
    u64 r;
    asm("mov.b64 %0, {%1, %2};" : "=l"(r) : "r"(__float_as_uint(lo)), "r"(__float_as_uint(hi)));
    return r;
}
__device__ __forceinline__ float2 upk2(u64 v) {
    unsigned int a, b;
    asm("mov.b64 {%0, %1}, %2;" : "=r"(a), "=r"(b) : "l"(v));
    return make_float2(__uint_as_float(a), __uint_as_float(b));
}
__device__ __forceinline__ u64 ffma2(u64 a, u64 b, u64 c) {
    u64 d;
    asm("fma.rn.f32x2 %0, %1, %2, %3;" : "=l"(d) : "l"(a), "l"(b), "l"(c));
    return d;
}

__device__ __forceinline__ float tanh_f(float x) {
    // exact at extremes, ~1e-6 abs error mid-range; independent of fast-math flags
    float e = __expf(2.0f * x);
    return 1.0f - 2.0f / (e + 1.0f);
}

// Branch-free float atomic max via int/uint monotone mapping.
// Requires init bit pattern 0xFFFFFFFF (acts below every float in both orders).
__device__ __forceinline__ void atomicMaxF(float* addr, float v) {
    if (v >= 0.0f) atomicMax((int*)addr, __float_as_int(v));
    else           atomicMin((unsigned int*)addr, __float_as_uint(v));
}

// ======================================================================
// Kernel 0a: detect edge_index dtype.
// Node ids < 50000 < 2^16, so for int64 every odd 32-bit word is 0.
// ======================================================================
__global__ void detect_idx(const int* __restrict__ ei32) {
    int t = threadIdx.x;                 // 256 threads
    int v = ei32[2 * t + 1];
    int any = __syncthreads_or(v != 0);
    if (t == 0) g_idx64 = (any == 0) ? 1 : 0;
}

// ======================================================================
// Kernel 0b: normalize edge_index -> int32 g_ei[2*EE]
// ======================================================================
__global__ __launch_bounds__(256) void convert_idx(const void* __restrict__ ei) {
    int i = blockIdx.x * 256 + threadIdx.x;
    if (i >= 2 * EE) return;
    if (g_idx64) g_ei[i] = (int)((const long long*)ei)[i];
    else         g_ei[i] = ((const int*)ei)[i];
}

// ======================================================================
// Kernel 1: node GEMM  g_xf = x @ [W_src | W_dst]   (50000x256 @ 256x256)
// 128x128 tile, BK=8, 256 threads, 8x8 micro-tile via FFMA2 (4 col-pairs)
// ======================================================================
__global__ __launch_bounds__(256) void gemm_node(const float* __restrict__ x,
                                                 const float* __restrict__ Wsrc,
                                                 const float* __restrict__ Wdst) {
    __shared__ __align__(16) u64   As2[8 * 128]; // [k][m], float duplicated in both halves
    __shared__ __align__(16) float Bs[8 * 128];  // [k][n]

    const int cb = blockIdx.y;                  // 0 -> W_src cols, 1 -> W_dst cols
    const float* __restrict__ W = cb ? Wdst : Wsrc;
    const int m0 = blockIdx.x * 128;
    const int t  = threadIdx.x;
    const int tx = t & 15;        // n-group (8 cols = 4 pairs)
    const int ty = t >> 4;        // m-group (8 rows)

    u64 acc[8][4];
#pragma unroll
    for (int i = 0; i < 8; i++)
#pragma unroll
        for (int j = 0; j < 4; j++) acc[i][j] = 0ULL;

    const int ar = t >> 1;            // A tile row 0..127
    const int ak = (t & 1) * 4;       // A tile k offset
    const int bk = t >> 5;            // B tile k row 0..7
    const int bc = (t & 31) * 4;      // B tile col

    const int arow = m0 + ar;
    const bool a_ok = (arow < NN);

    for (int k0 = 0; k0 < 256; k0 += 8) {
        float4 av = make_float4(0.f, 0.f, 0.f, 0.f);
        if (a_ok) av = *(const float4*)&x[(size_t)arow * 256 + k0 + ak];
        float4 bv = *(const float4*)&W[(size_t)(k0 + bk) * 128 + bc];

        __syncthreads();
        As2[(ak + 0) * 128 + ar] = pk2(av.x, av.x);
        As2[(ak + 1) * 128 + ar] = pk2(av.y, av.y);
        As2[(ak + 2) * 128 + ar] = pk2(av.z, av.z);
        As2[(ak + 3) * 128 + ar] = pk2(av.w, av.w);
        *(float4*)&Bs[bk * 128 + bc] = bv;
        __syncthreads();

#pragma unroll
        for (int k = 0; k < 8; k++) {
            u64 a2[8];
#pragma unroll
            for (int i = 0; i < 8; i++) a2[i] = As2[k * 128 + ty * 8 + i];
            const u64* bp = (const u64*)&Bs[k * 128 + tx * 8];
            u64 b2[4];
#pragma unroll
            for (int j = 0; j < 4; j++) b2[j] = bp[j];
#pragma unroll
            for (int i = 0; i < 8; i++)
#pragma unroll
                for (int j = 0; j < 4; j++) acc[i][j] = ffma2(a2[i], b2[j], acc[i][j]);
        }
    }

#pragma unroll
    for (int i = 0; i < 8; i++) {
        int row = m0 + ty * 8 + i;
        if (row < NN) {
            u64* op = (u64*)&g_xf[(size_t)row * 256 + cb * 128 + tx * 8];
#pragma unroll
            for (int j = 0; j < 4; j++) op[j] = acc[i][j];
        }
    }
}

// ======================================================================
// Kernel 2 (fused): e_feat GEMM + attention logits + decay + segment max
//   block = 256 threads = 8 warps; each warp owns 4 edges (32 per block).
//   Lane l owns channels [4l, 4l+4)  (head = l>>3).
//   Register-lean (<=64 regs, 4 blocks/SM) for gather-latency hiding.
// ======================================================================
__global__ __launch_bounds__(256, 4) void edge_attn(const float* __restrict__ eattr,
                                                    const float* __restrict__ dw,
                                                    const float* __restrict__ Wedge,
                                                    const float* __restrict__ att,
                                                    const float* __restrict__ sscale,
                                                    float* __restrict__ araw,
                                                    float* __restrict__ adec) {
    __shared__ __align__(16) float Ws[32 * 128]; // W_edge, 16KB
    const int t = threadIdx.x;
#pragma unroll
    for (int i = 0; i < 4; i++)
        ((float4*)Ws)[t + 256 * i] = ((const float4*)Wedge)[t + 256 * i];
    __syncthreads();

    const int w = t >> 5, l = t & 31;
    const int e0 = blockIdx.x * 32 + w * 4;

    const float4 att4 = *(const float4*)&att[4 * l];
    const float  sc   = sscale[l >> 3];

    // edge_attr rows across lanes: lane l holds eattr[e0+j][l]
    float ear[4];
#pragma unroll
    for (int j = 0; j < 4; j++) ear[j] = eattr[(size_t)(e0 + j) * 32 + l];

    // -------- phase A: e_feat for 4 edges x 4 channels, FFMA2 ----------
    u64 acc[4][2];
#pragma unroll
    for (int j = 0; j < 4; j++) { acc[j][0] = 0ULL; acc[j][1] = 0ULL; }

#pragma unroll
    for (int k = 0; k < 32; k++) {
        float4 w4 = *(const float4*)&Ws[k * 128 + 4 * l];
        u64 w01 = pk2(w4.x, w4.y);
        u64 w23 = pk2(w4.z, w4.w);
#pragma unroll
        for (int j = 0; j < 4; j++) {
            float a = __shfl_sync(0xffffffffu, ear[j], k);
            u64 a2 = pk2(a, a);
            acc[j][0] = ffma2(a2, w01, acc[j][0]);
            acc[j][1] = ffma2(a2, w23, acc[j][1]);
        }
    }

    // -------- phase B: tanh + att-dot + per-head reduce + decay --------
#pragma unroll
    for (int j = 0; j < 4; j++) {
        const int ge  = e0 + j;
        const int src = g_ei[ge];
        const int dst = g_ei[EE + ge];

        float4 xs = *(const float4*)&g_xf[(size_t)src * 256 + 4 * l];
        float4 xd = *(const float4*)&g_xf[(size_t)dst * 256 + 128 + 4 * l];
        float2 e01 = upk2(acc[j][0]);
        float2 e23 = upk2(acc[j][1]);

        float p = tanh_f(xs.x + xd.x + e01.x) * att4.x
                + tanh_f(xs.y + xd.y + e01.y) * att4.y
                + tanh_f(xs.z + xd.z + e23.x) * att4.z
                + tanh_f(xs.w + xd.w + e23.y) * att4.w;

        // reduce over the 8 lanes of this head -> every lane has its head's sum
        p += __shfl_xor_sync(0xffffffffu, p, 1);
        p += __shfl_xor_sync(0xffffffffu, p, 2);
        p += __shfl_xor_sync(0xffffffffu, p, 4);

        // spatial decay (per lane's head)
        float dwj = dw[ge];
        float dec = __expf(sc * __logf(dwj));
        float ad  = p * dec;

        // head leaders (lanes 0,8,16,24) store scalars directly: 4 scalar
        // stores to consecutive addresses coalesce into one 16B transaction
        if ((l & 7) == 0) {
            const int h = l >> 3;
            araw[(size_t)ge * 4 + h] = p;
            adec[(size_t)ge * 4 + h] = ad;
            atomicMaxF(&g_m[dst * 4 + h], ad);
        }
    }
}

// ======================================================================
// Kernel 3: ea = exp(alpha - m[dst]); s[dst] += ea.  One thread per edge,
//           float4 across the 4 heads + one red.v4 per edge.
// ======================================================================
__global__ __launch_bounds__(256) void pass_exp(float* __restrict__ buf) {
    int e = blockIdx.x * 256 + threadIdx.x;
    if (e >= EE) return;
    int dst = g_ei[EE + e];
    float4 a = *(const float4*)&buf[(size_t)e * 4];
    float4 m = *(const float4*)&g_m[dst * 4];
    float4 ea;
    ea.x = __expf(a.x - m.x);
    ea.y = __expf(a.y - m.y);
    ea.z = __expf(a.z - m.z);
    ea.w = __expf(a.w - m.w);
    *(float4*)&buf[(size_t)e * 4] = ea;
    float* sp = &g_s[dst * 4];
    asm volatile("red.global.add.v4.f32 [%0], {%1, %2, %3, %4};"
                 :: "l"(sp), "f"(ea.x), "f"(ea.y), "f"(ea.z), "f"(ea.w)
                 : "memory");
}

// ======================================================================
// Kernel 4: normalize + aggregate.  One warp per edge.
//   alpha_norm = ea/(s[dst]+1e-8) (written back to buf)
//   out[dst, ch] += x_src[src, ch] * alpha_norm[head(ch)]   via red.v4.f32
// ======================================================================
__global__ __launch_bounds__(256) void pass_agg(float* __restrict__ buf,
                                                float* __restrict__ outf) {
    int gw = (blockIdx.x * 256 + threadIdx.x) >> 5;
    if (gw >= EE) return;
    int l  = threadIdx.x & 31;
    int ge = gw;
    int src = g_ei[ge];
    int dst = g_ei[EE + ge];

    float4 ea4 = *(const float4*)&buf[(size_t)ge * 4];
    float4 s4  = *(const float4*)&g_s[dst * 4];
    float4 an;
    an.x = ea4.x / (s4.x + 1e-8f);
    an.y = ea4.y / (s4.y + 1e-8f);
    an.z = ea4.z / (s4.z + 1e-8f);
    an.w = ea4.w / (s4.w + 1e-8f);
    if (l == 0) *(float4*)&buf[(size_t)ge * 4] = an;

    float anh = (l < 8) ? an.x : (l < 16) ? an.y : (l < 24) ? an.z : an.w;
    float4 xs = *(const float4*)&g_xf[(size_t)src * 256 + 4 * l];

    float* dp = &outf[(size_t)dst * 128 + 4 * l];
    asm volatile("red.global.add.v4.f32 [%0], {%1, %2, %3, %4};"
                 :: "l"(dp), "f"(xs.x * anh), "f"(xs.y * anh), "f"(xs.z * anh), "f"(xs.w * anh)
                 : "memory");
}

// ======================================================================
// Launch
// Inputs (metadata order):
//  0 x[N,256] f32 | 1 edge_index[2,E] int32 OR int64 (auto-detected)
//  2 edge_attr[E,32] f32 | 3 dist_weight[E] f32 | 4 W_src[256,128]
//  5 W_dst[256,128] | 6 W_edge[32,128] | 7 att[1,4,32] | 8 spatial_scale[4]
// Output: out[N*128] (+ alpha_norm[E*4] + alpha_raw[E*4] if out_size allows)
// ======================================================================
extern "C" void kernel_launch(void* const* d_in, const int* in_sizes, int n_in,
                              void* d_out, int out_size) {
    const float* x      = (const float*)d_in[0];
    const void*  ei     = d_in[1];
    const float* eattr  = (const float*)d_in[2];
    const float* dwv    = (const float*)d_in[3];
    const float* Wsrc   = (const float*)d_in[4];
    const float* Wdst   = (const float*)d_in[5];
    const float* Wedge  = (const float*)d_in[6];
    const float* att    = (const float*)d_in[7];
    const float* sscale = (const float*)d_in[8];

    float* outf = (float*)d_out; // [N,128] always first

    // alpha buffers: inside d_out if it can hold all three outputs, else scratch
    const long long full = (long long)NN * HC + 2LL * EE * HH; // 12,800,000
    float *anorm, *araw;
    if ((long long)out_size >= full) {
        anorm = outf + (size_t)NN * HC;
        araw  = anorm + (size_t)EE * HH;
    } else {
        void *pa = 0, *pr = 0;
        cudaGetSymbolAddress(&pa, g_an);
        cudaGetSymbolAddress(&pr, g_ar);
        anorm = (float*)pa;
        araw  = (float*)pr;
    }

    // init: out=0, m="-inf" bit pattern (0xFF), s=0
    cudaMemsetAsync(outf, 0, (size_t)NN * HC * sizeof(float), 0);
    void *pm = 0, *ps = 0;
    cudaGetSymbolAddress(&pm, g_m);
    cudaGetSymbolAddress(&ps, g_s);
    cudaMemsetAsync(pm, 0xFF, (size_t)NN * HH * sizeof(float), 0);
    cudaMemsetAsync(ps, 0x00, (size_t)NN * HH * sizeof(float), 0);

    detect_idx<<<1, 256>>>((const int*)ei);
    convert_idx<<<(2 * EE + 255) / 256, 256>>>(ei);
    gemm_node<<<dim3((NN + 127) / 128, 2), 256>>>(x, Wsrc, Wdst);
    edge_attn<<<EE / 32, 256>>>(eattr, dwv, Wedge, att, sscale, araw, anorm);
    pass_exp<<<(EE + 255) / 256, 256>>>(anorm);
    pass_agg<<<(EE * 32) / 256, 256>>>(anorm, outf);
}